// round 3
// baseline (speedup 1.0000x reference)
#include <cuda_runtime.h>
#include <cstdint>

// Problem constants (fixed by setup_inputs):
//   P: [N=12, T=4096, D=2048] fp32, row-major
//   subgroup_indices: [2, 6] = arange(12)  (dtype int32 or int64 depending on JAX x64)
//   out: [1, T, 2*D] fp32 ; out[t, s*D + d] = max_{g<6} P[idx[s*6+g], t, d]
//
// Pure HBM-streaming: 402.7 MB read + 67.1 MB write, zero reuse.
// One thread per output float4: 6 coalesced float4 loads + 1 float4 store.

#define T_FRAMES   4096
#define D_DIM      2048
#define D4         (D_DIM / 4)          // 512 float4 per (n, t) row
#define OUT_F4     (T_FRAMES * 2 * D4)  // total output float4 = 4,194,304
#define FRAME_F4   (2 * D4)             // 1024 float4 per output frame
#define TD4        ((long long)T_FRAMES * D4)

__global__ __launch_bounds__(256) void subgroup_maxpool_kernel(
    const float4* __restrict__ P4,
    const int*    __restrict__ idx_words,   // raw words of the index buffer
    float4*       __restrict__ out4)
{
    int i = blockIdx.x * blockDim.x + threadIdx.x;
    if (i >= OUT_F4) return;

    // Decode output coordinate: frame t, subgroup s, float4-column d4
    int t   = i >> 10;            // / FRAME_F4 (1024)
    int rem = i & (FRAME_F4 - 1);
    int s   = rem >> 9;           // / D4 (512)
    int d4  = rem & (D4 - 1);

    // Detect index dtype: int64 arange -> words = 0,0,1,0,2,0,... (word[1]==0)
    //                     int32 arange -> words = 0,1,2,...       (word[1]==1)
    const bool is64 = (idx_words[1] == 0);

    const long long col = (long long)t * D4 + d4;

    float4 m;
    #pragma unroll
    for (int g = 0; g < 6; ++g) {
        const int j = s * 6 + g;
        const int n = is64 ? idx_words[2 * j] : idx_words[j];
        float4 v = __ldg(&P4[(long long)n * TD4 + col]);
        if (g == 0) {
            m = v;
        } else {
            m.x = fmaxf(m.x, v.x);
            m.y = fmaxf(m.y, v.y);
            m.z = fmaxf(m.z, v.z);
            m.w = fmaxf(m.w, v.w);
        }
    }
    out4[i] = m;
}

extern "C" void kernel_launch(void* const* d_in, const int* in_sizes, int n_in,
                              void* d_out, int out_size)
{
    const float4* P4  = (const float4*)d_in[0];
    const int*    idx = (const int*)d_in[1];
    float4*       out = (float4*)d_out;

    const int threads = 256;
    const int blocks  = (OUT_F4 + threads - 1) / threads;  // 16384
    subgroup_maxpool_kernel<<<blocks, threads>>>(P4, idx, out);
}

// round 4
// speedup vs baseline: 1.0060x; 1.0060x over previous
#include <cuda_runtime.h>
#include <cstdint>

// Problem constants (fixed by setup_inputs):
//   P: [N=12, T=4096, D=2048] fp32, row-major
//   subgroup_indices: [2, 6] = arange(12)  (int32 or int64 depending on JAX x64)
//   out: [1, T, 2*D] fp32 ; out[t, s*D + d] = max_{g<6} P[idx[s*6+g], t, d]
//
// Pure HBM streaming (403 MB read + 67 MB write, zero reuse) -> every byte is
// touch-once. Use streaming cache hints (__ldcs / __stcs, evict-first) so the
// read and write streams don't fight over L2 residency, maximizing DRAM
// scheduling efficiency. One thread per output float4: 6 coalesced float4
// loads + 1 float4 store, MLP=6, 32 regs, high occupancy.

#define T_FRAMES   4096
#define D_DIM      2048
#define D4         (D_DIM / 4)          // 512 float4 per (n, t) row
#define OUT_F4     (T_FRAMES * 2 * D4)  // total output float4 = 4,194,304
#define FRAME_F4   (2 * D4)             // 1024 float4 per output frame
#define TD4        ((long long)T_FRAMES * D4)

__global__ __launch_bounds__(256) void subgroup_maxpool_kernel(
    const float4* __restrict__ P4,
    const int*    __restrict__ idx_words,   // raw words of the index buffer
    float4*       __restrict__ out4)
{
    int i = blockIdx.x * blockDim.x + threadIdx.x;
    if (i >= OUT_F4) return;

    // Decode output coordinate: frame t, subgroup s, float4-column d4
    int t   = i >> 10;            // / FRAME_F4 (1024)
    int rem = i & (FRAME_F4 - 1);
    int s   = rem >> 9;           // / D4 (512)
    int d4  = rem & (D4 - 1);

    // Detect index dtype: int64 arange -> words = 0,0,1,0,2,0,... (word[1]==0)
    //                     int32 arange -> words = 0,1,2,...       (word[1]==1)
    const bool is64 = (idx_words[1] == 0);

    const long long col = (long long)t * D4 + d4;

    float4 m;
    #pragma unroll
    for (int g = 0; g < 6; ++g) {
        const int j = s * 6 + g;
        const int n = is64 ? idx_words[2 * j] : idx_words[j];
        // Streaming load: touch-once data, evict-first in L1/L2.
        float4 v = __ldcs(&P4[(long long)n * TD4 + col]);
        if (g == 0) {
            m = v;
        } else {
            m.x = fmaxf(m.x, v.x);
            m.y = fmaxf(m.y, v.y);
            m.z = fmaxf(m.z, v.z);
            m.w = fmaxf(m.w, v.w);
        }
    }
    // Streaming store: never read back, don't pollute L2.
    __stcs(&out4[i], m);
}

extern "C" void kernel_launch(void* const* d_in, const int* in_sizes, int n_in,
                              void* d_out, int out_size)
{
    const float4* P4  = (const float4*)d_in[0];
    const int*    idx = (const int*)d_in[1];
    float4*       out = (float4*)d_out;

    const int threads = 256;
    const int blocks  = (OUT_F4 + threads - 1) / threads;  // 16384
    subgroup_maxpool_kernel<<<blocks, threads>>>(P4, idx, out);
}